// round 1
// baseline (speedup 1.0000x reference)
#include <cuda_runtime.h>
#include <math.h>

#define B_ 32
#define S_ 1024
#define D_ 512
#define H_ 8
#define DH_ 64
#define L_ 3
#define FF_ 2048
#define C_ 6
#define BS_ (B_*S_)

// ---------------- scratch (device globals; no allocations allowed) ----------
static __device__ float g_x[(size_t)BS_*D_];          // 64 MB residual stream
static __device__ float g_qkv[(size_t)BS_*3*D_];      // 192 MB
static __device__ float g_scores[(size_t)B_*H_*S_*S_];// 1 GB attention scores/probs
static __device__ float g_o[(size_t)BS_*D_];          // 64 MB attention output
static __device__ float g_p[(size_t)BS_*D_];          // 64 MB proj output
static __device__ float g_pool[B_*D_];
static __device__ float g_h1[B_*FF_];

// ---------------- embedding + sinusoidal PE --------------------------------
__global__ void __launch_bounds__(256) embed_kernel(const int* __restrict__ tokens,
                                                    const float* __restrict__ emb) {
    int idx = blockIdx.x * 256 + threadIdx.x;   // 0 .. BS_*D_-1
    int d  = idx & (D_ - 1);
    int bs = idx >> 9;                          // D_ = 512
    int s  = bs & (S_ - 1);
    int tok = tokens[bs];
    float div = expf((float)(d & ~1) * (-9.210340371976184f / (float)D_)); // ln(10000)
    float ang = (float)s * div;
    float pe = (d & 1) ? cosf(ang) : sinf(ang);
    g_x[idx] = emb[(size_t)tok * D_ + d] + pe;
}

// ---------------- 128x128x16 register-tiled SGEMM ---------------------------
// C[M,N] = A[M,K] @ B[K,N] (+ bias per column). M,N multiples of 128, K of 16.
__global__ void __launch_bounds__(256) sgemm128(const float* __restrict__ A,
                                                const float* __restrict__ Bm,
                                                const float* __restrict__ bias,
                                                float* __restrict__ Cm,
                                                int N, int K) {
    __shared__ float As[16][128];
    __shared__ float Bs[16][128];
    int tid = threadIdx.x;
    const float* Ab = A + (size_t)blockIdx.y * 128 * K;
    const float* Bb = Bm + (size_t)blockIdx.x * 128;
    int arow = tid >> 2;            // 0..63
    int acol = (tid & 3) << 2;      // 0,4,8,12
    int brow = tid >> 5;            // 0..7
    int bcol = (tid & 31) << 2;     // 0..124
    int tx = tid & 15, ty = tid >> 4;
    float acc[8][8];
    #pragma unroll
    for (int i = 0; i < 8; i++)
        #pragma unroll
        for (int j = 0; j < 8; j++) acc[i][j] = 0.f;

    for (int k0 = 0; k0 < K; k0 += 16) {
        float4 a0 = *(const float4*)(Ab + (size_t)arow * K + k0 + acol);
        float4 a1 = *(const float4*)(Ab + (size_t)(arow + 64) * K + k0 + acol);
        float4 b0 = *(const float4*)(Bb + (size_t)(k0 + brow) * N + bcol);
        float4 b1 = *(const float4*)(Bb + (size_t)(k0 + brow + 8) * N + bcol);
        As[acol+0][arow] = a0.x; As[acol+1][arow] = a0.y;
        As[acol+2][arow] = a0.z; As[acol+3][arow] = a0.w;
        As[acol+0][arow+64] = a1.x; As[acol+1][arow+64] = a1.y;
        As[acol+2][arow+64] = a1.z; As[acol+3][arow+64] = a1.w;
        *(float4*)&Bs[brow][bcol]   = b0;
        *(float4*)&Bs[brow+8][bcol] = b1;
        __syncthreads();
        #pragma unroll
        for (int k = 0; k < 16; k++) {
            float ra[8], rb[8];
            *(float4*)&ra[0] = *(float4*)&As[k][ty*8];
            *(float4*)&ra[4] = *(float4*)&As[k][ty*8+4];
            *(float4*)&rb[0] = *(float4*)&Bs[k][tx*8];
            *(float4*)&rb[4] = *(float4*)&Bs[k][tx*8+4];
            #pragma unroll
            for (int i = 0; i < 8; i++)
                #pragma unroll
                for (int j = 0; j < 8; j++)
                    acc[i][j] = fmaf(ra[i], rb[j], acc[i][j]);
        }
        __syncthreads();
    }
    float bv[8];
    #pragma unroll
    for (int j = 0; j < 8; j++)
        bv[j] = bias ? bias[blockIdx.x*128 + tx*8 + j] : 0.f;
    float* Cb = Cm + ((size_t)blockIdx.y * 128 + ty*8) * N + (size_t)blockIdx.x * 128 + tx*8;
    #pragma unroll
    for (int i = 0; i < 8; i++) {
        float4 w0 = make_float4(acc[i][0]+bv[0], acc[i][1]+bv[1], acc[i][2]+bv[2], acc[i][3]+bv[3]);
        float4 w1 = make_float4(acc[i][4]+bv[4], acc[i][5]+bv[5], acc[i][6]+bv[6], acc[i][7]+bv[7]);
        *(float4*)(Cb + (size_t)i * N)     = w0;
        *(float4*)(Cb + (size_t)i * N + 4) = w1;
    }
}

// ---------------- QK^T: scores[bh, q, k] = (Q.K)/8 --------------------------
// grid (S/64, S/64, B*H), 256 threads, 64x64 output tile, K=64
__global__ void __launch_bounds__(256) qk_kernel() {
    int bh = blockIdx.z;
    int b = bh >> 3, h = bh & 7;
    int sq0 = blockIdx.y * 64, sk0 = blockIdx.x * 64;
    __shared__ float Qs[64][64];   // [d][q]
    __shared__ float Ks[64][64];   // [d][k]
    int tid = threadIdx.x;
    const float* qb = g_qkv + ((size_t)(b*S_ + sq0)) * 1536 + h*192;
    const float* kb = g_qkv + ((size_t)(b*S_ + sk0)) * 1536 + h*192 + 64;
    #pragma unroll
    for (int it = 0; it < 4; it++) {
        int lin = tid + it * 256;
        int row = lin >> 4;
        int c4  = (lin & 15) << 2;
        float4 q4 = *(const float4*)(qb + (size_t)row * 1536 + c4);
        Qs[c4+0][row]=q4.x; Qs[c4+1][row]=q4.y; Qs[c4+2][row]=q4.z; Qs[c4+3][row]=q4.w;
        float4 k4 = *(const float4*)(kb + (size_t)row * 1536 + c4);
        Ks[c4+0][row]=k4.x; Ks[c4+1][row]=k4.y; Ks[c4+2][row]=k4.z; Ks[c4+3][row]=k4.w;
    }
    __syncthreads();
    int tx = tid & 15, ty = tid >> 4;
    float acc[4][4];
    #pragma unroll
    for (int i = 0; i < 4; i++)
        #pragma unroll
        for (int j = 0; j < 4; j++) acc[i][j] = 0.f;
    #pragma unroll 16
    for (int d = 0; d < 64; d++) {
        float4 ra = *(float4*)&Qs[d][ty*4];
        float4 rb = *(float4*)&Ks[d][tx*4];
        float a[4] = {ra.x, ra.y, ra.z, ra.w};
        float c[4] = {rb.x, rb.y, rb.z, rb.w};
        #pragma unroll
        for (int i = 0; i < 4; i++)
            #pragma unroll
            for (int j = 0; j < 4; j++)
                acc[i][j] = fmaf(a[i], c[j], acc[i][j]);
    }
    float* srow = g_scores + ((size_t)bh * S_ + sq0 + ty*4) * S_ + sk0 + tx*4;
    #pragma unroll
    for (int i = 0; i < 4; i++) {
        float4 w = make_float4(acc[i][0]*0.125f, acc[i][1]*0.125f,
                               acc[i][2]*0.125f, acc[i][3]*0.125f);
        *(float4*)(srow + (size_t)i * S_) = w;
    }
}

// ---------------- row softmax over scores (1024 cols) ------------------------
__global__ void __launch_bounds__(256) softmax_kernel() {
    size_t row = blockIdx.x;
    float* p = g_scores + row * S_;
    int tid = threadIdx.x;
    float4 v = *(float4*)(p + tid * 4);
    float m = fmaxf(fmaxf(v.x, v.y), fmaxf(v.z, v.w));
    #pragma unroll
    for (int o = 16; o; o >>= 1) m = fmaxf(m, __shfl_xor_sync(0xffffffffu, m, o));
    __shared__ float sm[8], ss[8];
    if ((tid & 31) == 0) sm[tid >> 5] = m;
    __syncthreads();
    m = sm[0];
    #pragma unroll
    for (int w = 1; w < 8; w++) m = fmaxf(m, sm[w]);
    v.x = __expf(v.x - m); v.y = __expf(v.y - m);
    v.z = __expf(v.z - m); v.w = __expf(v.w - m);
    float s = v.x + v.y + v.z + v.w;
    #pragma unroll
    for (int o = 16; o; o >>= 1) s += __shfl_xor_sync(0xffffffffu, s, o);
    if ((tid & 31) == 0) ss[tid >> 5] = s;
    __syncthreads();
    s = 0.f;
    #pragma unroll
    for (int w = 0; w < 8; w++) s += ss[w];
    float inv = 1.0f / s;
    v.x *= inv; v.y *= inv; v.z *= inv; v.w *= inv;
    *(float4*)(p + tid * 4) = v;
}

// ---------------- AV: o[b,s, h*64+d] = P @ V --------------------------------
// grid (S/64, B*H), 256 threads, 64x64 tile (queries x dh), K=1024
__global__ void __launch_bounds__(256) av_kernel() {
    int bh = blockIdx.y;
    int b = bh >> 3, h = bh & 7;
    int sq0 = blockIdx.x * 64;
    __shared__ float Ps[64][64];   // [k][q]
    __shared__ float Vs[64][64];   // [k][d]
    int tid = threadIdx.x;
    int tx = tid & 15, ty = tid >> 4;
    float acc[4][4];
    #pragma unroll
    for (int i = 0; i < 4; i++)
        #pragma unroll
        for (int j = 0; j < 4; j++) acc[i][j] = 0.f;
    const float* prow = g_scores + ((size_t)bh * S_ + sq0) * S_;
    const float* vb = g_qkv + ((size_t)(b*S_)) * 1536 + h*192 + 128;
    for (int k0 = 0; k0 < S_; k0 += 64) {
        #pragma unroll
        for (int it = 0; it < 4; it++) {
            int lin = tid + it * 256;
            int row = lin >> 4;
            int c4  = (lin & 15) << 2;
            float4 p4 = *(const float4*)(prow + (size_t)row * S_ + k0 + c4);
            Ps[c4+0][row]=p4.x; Ps[c4+1][row]=p4.y; Ps[c4+2][row]=p4.z; Ps[c4+3][row]=p4.w;
            float4 v4 = *(const float4*)(vb + (size_t)(k0 + row) * 1536 + c4);
            *(float4*)&Vs[row][c4] = v4;
        }
        __syncthreads();
        #pragma unroll 16
        for (int kk = 0; kk < 64; kk++) {
            float4 ra = *(float4*)&Ps[kk][ty*4];
            float4 rb = *(float4*)&Vs[kk][tx*4];
            float a[4] = {ra.x, ra.y, ra.z, ra.w};
            float c[4] = {rb.x, rb.y, rb.z, rb.w};
            #pragma unroll
            for (int i = 0; i < 4; i++)
                #pragma unroll
                for (int j = 0; j < 4; j++)
                    acc[i][j] = fmaf(a[i], c[j], acc[i][j]);
        }
        __syncthreads();
    }
    float* ob = g_o + ((size_t)(b*S_ + sq0 + ty*4)) * D_ + h*64 + tx*4;
    #pragma unroll
    for (int i = 0; i < 4; i++) {
        float4 w = make_float4(acc[i][0], acc[i][1], acc[i][2], acc[i][3]);
        *(float4*)(ob + (size_t)i * D_) = w;
    }
}

// ---------------- residual + bias + LayerNorm, x <- LN(p + bias + x) ---------
__global__ void __launch_bounds__(128) ln_kernel(const float* __restrict__ bias,
                                                 const float* __restrict__ gamma,
                                                 const float* __restrict__ beta) {
    size_t r = blockIdx.x;
    int tid = threadIdx.x;
    float4 o  = *(float4*)(g_p + r * D_ + tid * 4);
    float4 xr = *(float4*)(g_x + r * D_ + tid * 4);
    float4 bb = *(const float4*)(bias + tid * 4);
    float4 y;
    y.x = o.x + xr.x + bb.x; y.y = o.y + xr.y + bb.y;
    y.z = o.z + xr.z + bb.z; y.w = o.w + xr.w + bb.w;
    __shared__ float sm[4], ss[4];
    float s = y.x + y.y + y.z + y.w;
    #pragma unroll
    for (int o2 = 16; o2; o2 >>= 1) s += __shfl_xor_sync(0xffffffffu, s, o2);
    if ((tid & 31) == 0) sm[tid >> 5] = s;
    __syncthreads();
    float mean = (sm[0] + sm[1] + sm[2] + sm[3]) * (1.0f / D_);
    float dx = y.x - mean, dy = y.y - mean, dz = y.z - mean, dw = y.w - mean;
    float sq = dx*dx + dy*dy + dz*dz + dw*dw;
    #pragma unroll
    for (int o2 = 16; o2; o2 >>= 1) sq += __shfl_xor_sync(0xffffffffu, sq, o2);
    if ((tid & 31) == 0) ss[tid >> 5] = sq;
    __syncthreads();
    float var = (ss[0] + ss[1] + ss[2] + ss[3]) * (1.0f / D_);
    float inv = rsqrtf(var + 1e-5f);
    float4 g = *(const float4*)(gamma + tid * 4);
    float4 be = *(const float4*)(beta + tid * 4);
    float4 out;
    out.x = dx * inv * g.x + be.x; out.y = dy * inv * g.y + be.y;
    out.z = dz * inv * g.z + be.z; out.w = dw * inv * g.w + be.w;
    *(float4*)(g_x + r * D_ + tid * 4) = out;
}

// ---------------- mean pool over sequence ------------------------------------
__global__ void __launch_bounds__(512) pool_kernel() {
    int b = blockIdx.x, d = threadIdx.x;
    const float* base = g_x + (size_t)b * S_ * D_ + d;
    float s = 0.f;
    for (int i = 0; i < S_; i++) s += base[(size_t)i * D_];
    g_pool[b * D_ + d] = s * (1.0f / S_);
}

// ---------------- MLP ---------------------------------------------------------
__global__ void __launch_bounds__(256) mlp1_kernel(const float* __restrict__ w,
                                                   const float* __restrict__ bias) {
    int f = blockIdx.x * 256 + threadIdx.x;
    int b = blockIdx.y;
    float acc = bias[f];
    const float* pr = g_pool + b * D_;
    for (int d = 0; d < D_; d++) acc = fmaf(pr[d], w[(size_t)d * FF_ + f], acc);
    g_h1[b * FF_ + f] = fmaxf(acc, 0.f);
}

__global__ void __launch_bounds__(192) mlp2_kernel(const float* __restrict__ w,
                                                   const float* __restrict__ bias,
                                                   float* __restrict__ out) {
    int t = threadIdx.x;            // 192 = B_*C_
    int b = t / C_, c = t % C_;
    float acc = bias[c];
    const float* hr = g_h1 + b * FF_;
    for (int f = 0; f < FF_; f++) acc = fmaf(hr[f], w[f * C_ + c], acc);
    out[b * C_ + c] = acc;
}

// ---------------- launch ------------------------------------------------------
extern "C" void kernel_launch(void* const* d_in, const int* in_sizes, int n_in,
                              void* d_out, int out_size) {
    const int*   tokens = (const int*)d_in[0];
    const float* emb    = (const float*)d_in[1];
    const float* qkv_w  = (const float*)d_in[2];
    const float* qkv_b  = (const float*)d_in[3];
    const float* fc_w   = (const float*)d_in[4];
    const float* fc_b   = (const float*)d_in[5];
    const float* gamma  = (const float*)d_in[6];
    const float* beta   = (const float*)d_in[7];
    const float* fc1_w  = (const float*)d_in[8];
    const float* fc1_b  = (const float*)d_in[9];
    const float* fc2_w  = (const float*)d_in[10];
    const float* fc2_b  = (const float*)d_in[11];
    float* out = (float*)d_out;
    (void)in_sizes; (void)n_in; (void)out_size;

    float *x, *qkv, *o, *p;
    cudaGetSymbolAddress((void**)&x,   g_x);
    cudaGetSymbolAddress((void**)&qkv, g_qkv);
    cudaGetSymbolAddress((void**)&o,   g_o);
    cudaGetSymbolAddress((void**)&p,   g_p);

    embed_kernel<<<(BS_ * D_) / 256, 256>>>(tokens, emb);

    for (int l = 0; l < L_; l++) {
        // qkv = x @ qkv_w[l] + qkv_b[l]
        sgemm128<<<dim3(3 * D_ / 128, BS_ / 128), 256>>>(
            x, qkv_w + (size_t)l * D_ * 3 * D_, qkv_b + (size_t)l * 3 * D_,
            qkv, 3 * D_, D_);
        // attention
        qk_kernel<<<dim3(S_ / 64, S_ / 64, B_ * H_), 256>>>();
        softmax_kernel<<<B_ * H_ * S_, 256>>>();
        av_kernel<<<dim3(S_ / 64, B_ * H_), 256>>>();
        // projection (bias folded into LN)
        sgemm128<<<dim3(D_ / 128, BS_ / 128), 256>>>(
            o, fc_w + (size_t)l * D_ * D_, (const float*)nullptr, p, D_, D_);
        // x = LN(p + fc_b[l] + x)
        ln_kernel<<<BS_, 128>>>(fc_b + (size_t)l * D_, gamma, beta);
    }

    pool_kernel<<<B_, 512>>>();
    mlp1_kernel<<<dim3(FF_ / 256, B_), 256>>>(fc1_w, fc1_b);
    mlp2_kernel<<<1, B_ * C_>>>(fc2_w, fc2_b, out);
}